// round 1
// baseline (speedup 1.0000x reference)
#include <cuda_runtime.h>
#include <cuda_bf16.h>

#define N_NODES 50000
#define N_EDGES 800000
#define EMB     100
#define EMB4    25          // float4 chunks per row
#define EPSN    1e-12f

// Scratch ping-pong buffers (allocation-free rule: __device__ globals)
__device__ float g_bufA[N_NODES * EMB];
__device__ float g_bufB[N_NODES * EMB];

// ---------------------------------------------------------------------------
// SpMM: y[row[e]] += val[e] * x[col[e]]   (edge-parallel, vec4 L2 atomics)
// One thread per (edge, float4-chunk). 25 adjacent threads share one edge.
// ---------------------------------------------------------------------------
__global__ void __launch_bounds__(256)
spmm_kernel(const int* __restrict__ rows, const int* __restrict__ cols,
            const float* __restrict__ vals, const float* __restrict__ x,
            float* __restrict__ y)
{
    unsigned idx = blockIdx.x * blockDim.x + threadIdx.x;
    if (idx >= (unsigned)N_EDGES * EMB4) return;
    unsigned e = idx / EMB4;          // const divide -> mul/shift
    unsigned c = idx - e * EMB4;

    float w  = __ldg(vals + e);
    int  col = __ldg(cols + e);
    int  row = __ldg(rows + e);

    float4 v = __ldg((const float4*)(x + (size_t)col * EMB) + c);
    v.x *= w; v.y *= w; v.z *= w; v.w *= w;

    float* dst = y + (size_t)row * EMB + c * 4;
#if __CUDA_ARCH__ >= 900
    asm volatile("red.global.add.v4.f32 [%0], {%1, %2, %3, %4};"
                 :: "l"(dst), "f"(v.x), "f"(v.y), "f"(v.z), "f"(v.w)
                 : "memory");
#else
    atomicAdd(dst + 0, v.x);
    atomicAdd(dst + 1, v.y);
    atomicAdd(dst + 2, v.z);
    atomicAdd(dst + 3, v.w);
#endif
}

// ---------------------------------------------------------------------------
// Row-normalize + accumulate into out (+ optional zeroing of the next scratch
// buffer, fused to avoid an extra pass). One warp per row.
//   out[row] (+)= a[layer] * x[row] / max(||x[row]||, eps)
// ---------------------------------------------------------------------------
template<bool FIRST, bool ZERO>
__global__ void __launch_bounds__(256)
norm_add_kernel(const float* __restrict__ x, float* __restrict__ out,
                float* __restrict__ zb, const float* __restrict__ a, int layer)
{
    int warp = (blockIdx.x * blockDim.x + threadIdx.x) >> 5;
    int lane = threadIdx.x & 31;
    if (warp >= N_NODES) return;

    const float4* xr = (const float4*)(x + (size_t)warp * EMB);
    float4 v = make_float4(0.f, 0.f, 0.f, 0.f);
    if (lane < EMB4) v = __ldg(xr + lane);

    float ss = v.x * v.x + v.y * v.y + v.z * v.z + v.w * v.w;
#pragma unroll
    for (int o = 16; o; o >>= 1) ss += __shfl_xor_sync(0xffffffffu, ss, o);

    float scale = __ldg(a + layer) / fmaxf(sqrtf(ss), EPSN);

    if (lane < EMB4) {
        float4* orow = (float4*)(out + (size_t)warp * EMB);
        float4 o;
        o.x = v.x * scale; o.y = v.y * scale; o.z = v.z * scale; o.w = v.w * scale;
        if (!FIRST) {
            float4 p = orow[lane];
            o.x += p.x; o.y += p.y; o.z += p.z; o.w += p.w;
        }
        orow[lane] = o;
        if (ZERO)
            ((float4*)(zb + (size_t)warp * EMB))[lane] = make_float4(0.f, 0.f, 0.f, 0.f);
    }
}

// ---------------------------------------------------------------------------
// Launch: inputs are adj_row, adj_col, adj_val, embedding, a (metadata order)
// ---------------------------------------------------------------------------
extern "C" void kernel_launch(void* const* d_in, const int* in_sizes, int n_in,
                              void* d_out, int out_size)
{
    const int*   adj_row = (const int*)  d_in[0];
    const int*   adj_col = (const int*)  d_in[1];
    const float* adj_val = (const float*)d_in[2];
    const float* emb     = (const float*)d_in[3];
    const float* a       = (const float*)d_in[4];
    float*       out     = (float*)d_out;

    float* bufA; cudaGetSymbolAddress((void**)&bufA, g_bufA);
    float* bufB; cudaGetSymbolAddress((void**)&bufB, g_bufB);

    const int NORM_BLOCKS = (N_NODES + 7) / 8;                  // 8 warps/block
    const int SPMM_THREADS = N_EDGES * EMB4;                    // 20M
    const int SPMM_BLOCKS = (SPMM_THREADS + 255) / 256;

    // layer 0: out = a0*normalize(emb); zero bufA
    norm_add_kernel<true,  true ><<<NORM_BLOCKS, 256>>>(emb,  out, bufA, a, 0);
    // x1 = A @ emb
    spmm_kernel<<<SPMM_BLOCKS, 256>>>(adj_row, adj_col, adj_val, emb, bufA);
    // out += a1*normalize(x1); zero bufB
    norm_add_kernel<false, true ><<<NORM_BLOCKS, 256>>>(bufA, out, bufB, a, 1);
    // x2 = A @ x1
    spmm_kernel<<<SPMM_BLOCKS, 256>>>(adj_row, adj_col, adj_val, bufA, bufB);
    // out += a2*normalize(x2); zero bufA (reuse)
    norm_add_kernel<false, true ><<<NORM_BLOCKS, 256>>>(bufB, out, bufA, a, 2);
    // x3 = A @ x2
    spmm_kernel<<<SPMM_BLOCKS, 256>>>(adj_row, adj_col, adj_val, bufB, bufA);
    // out += a3*normalize(x3)
    norm_add_kernel<false, false><<<NORM_BLOCKS, 256>>>(bufA, out, nullptr, a, 3);
}

// round 2
// speedup vs baseline: 1.1984x; 1.1984x over previous
#include <cuda_runtime.h>
#include <cuda_bf16.h>

#define N_NODES 50000
#define N_EDGES 800000
#define EMB     100
#define EMB4    25          // float4 chunks per row
#define EPSN    1e-12f
#define SCAN_B  256
#define NB_SCAN ((N_NODES + SCAN_B - 1) / SCAN_B)   // 196

// Scratch (allocation-free rule: __device__ globals)
__device__ float g_bufA[N_NODES * EMB];
__device__ float g_bufB[N_NODES * EMB];
__device__ int   g_deg[N_NODES];
__device__ int   g_cursor[N_NODES];
__device__ int   g_rowptr[N_NODES + 1];
__device__ int   g_blocksum[NB_SCAN];
__device__ int   g_blockoff[NB_SCAN];
__device__ int2  g_cells[N_EDGES];        // {col, val-as-int-bits}

// ---------------------------------------------------------------------------
// CSR build
// ---------------------------------------------------------------------------
__global__ void zero_kernel(int* __restrict__ deg, int* __restrict__ cur)
{
    int i = blockIdx.x * blockDim.x + threadIdx.x;
    if (i < N_NODES) { deg[i] = 0; cur[i] = 0; }
}

__global__ void hist_kernel(const int* __restrict__ rows, int* __restrict__ deg)
{
    int e = blockIdx.x * blockDim.x + threadIdx.x;
    if (e < N_EDGES) atomicAdd(&deg[rows[e]], 1);
}

// per-block sums of deg
__global__ void scan_k1(const int* __restrict__ deg, int* __restrict__ bsum)
{
    __shared__ int s[SCAN_B];
    int i = blockIdx.x * SCAN_B + threadIdx.x;
    int v = (i < N_NODES) ? deg[i] : 0;
    s[threadIdx.x] = v;
    __syncthreads();
    for (int off = SCAN_B >> 1; off; off >>= 1) {
        if (threadIdx.x < off) s[threadIdx.x] += s[threadIdx.x + off];
        __syncthreads();
    }
    if (threadIdx.x == 0) bsum[blockIdx.x] = s[0];
}

// exclusive scan of block sums (single block)
__global__ void scan_k2(const int* __restrict__ bsum, int* __restrict__ boff)
{
    __shared__ int s[SCAN_B];
    int t = threadIdx.x;
    int v = (t < NB_SCAN) ? bsum[t] : 0;
    s[t] = v;
    __syncthreads();
    for (int off = 1; off < SCAN_B; off <<= 1) {
        int add = (t >= off) ? s[t - off] : 0;
        __syncthreads();
        s[t] += add;
        __syncthreads();
    }
    if (t < NB_SCAN) boff[t] = s[t] - v;    // exclusive
}

// per-block exclusive scan + offset -> rowptr
__global__ void scan_k3(const int* __restrict__ deg, const int* __restrict__ boff,
                        int* __restrict__ rowptr)
{
    __shared__ int s[SCAN_B];
    int t = threadIdx.x;
    int i = blockIdx.x * SCAN_B + t;
    int v = (i < N_NODES) ? deg[i] : 0;
    s[t] = v;
    __syncthreads();
    for (int off = 1; off < SCAN_B; off <<= 1) {
        int add = (t >= off) ? s[t - off] : 0;
        __syncthreads();
        s[t] += add;
        __syncthreads();
    }
    if (i < N_NODES) rowptr[i] = boff[blockIdx.x] + s[t] - v;
    if (i == 0) rowptr[N_NODES] = N_EDGES;
}

__global__ void scatter_kernel(const int* __restrict__ rows,
                               const int* __restrict__ cols,
                               const float* __restrict__ vals,
                               const int* __restrict__ rowptr,
                               int* __restrict__ cur, int2* __restrict__ cells)
{
    int e = blockIdx.x * blockDim.x + threadIdx.x;
    if (e >= N_EDGES) return;
    int r = rows[e];
    int pos = rowptr[r] + atomicAdd(&cur[r], 1);
    cells[pos] = make_int2(cols[e], __float_as_int(vals[e]));
}

// ---------------------------------------------------------------------------
// CSR SpMM: warp per row, lanes 0..24 own one float4 chunk each; no atomics.
// ---------------------------------------------------------------------------
__global__ void __launch_bounds__(256)
spmm_csr_kernel(const int* __restrict__ rowptr, const int2* __restrict__ cells,
                const float* __restrict__ x, float* __restrict__ y)
{
    int warp = (blockIdx.x * blockDim.x + threadIdx.x) >> 5;
    int lane = threadIdx.x & 31;
    if (warp >= N_NODES) return;

    int p   = __ldg(rowptr + warp);
    int end = __ldg(rowptr + warp + 1);

    float4 acc = make_float4(0.f, 0.f, 0.f, 0.f);
    bool active = lane < EMB4;

    // unroll by 2 for MLP on the dependent index->gather chain
    for (; p + 1 < end; p += 2) {
        int2 cv0 = __ldg(cells + p);
        int2 cv1 = __ldg(cells + p + 1);
        if (active) {
            float4 v0 = __ldg((const float4*)(x + (size_t)cv0.x * EMB) + lane);
            float4 v1 = __ldg((const float4*)(x + (size_t)cv1.x * EMB) + lane);
            float w0 = __int_as_float(cv0.y);
            float w1 = __int_as_float(cv1.y);
            acc.x += w0 * v0.x; acc.y += w0 * v0.y;
            acc.z += w0 * v0.z; acc.w += w0 * v0.w;
            acc.x += w1 * v1.x; acc.y += w1 * v1.y;
            acc.z += w1 * v1.z; acc.w += w1 * v1.w;
        }
    }
    if (p < end) {
        int2 cv = __ldg(cells + p);
        if (active) {
            float4 v = __ldg((const float4*)(x + (size_t)cv.x * EMB) + lane);
            float w = __int_as_float(cv.y);
            acc.x += w * v.x; acc.y += w * v.y;
            acc.z += w * v.z; acc.w += w * v.w;
        }
    }
    if (active)
        ((float4*)(y + (size_t)warp * EMB))[lane] = acc;
}

// ---------------------------------------------------------------------------
// Row-normalize + accumulate into out. One warp per row.
// ---------------------------------------------------------------------------
template<bool FIRST>
__global__ void __launch_bounds__(256)
norm_add_kernel(const float* __restrict__ x, float* __restrict__ out,
                const float* __restrict__ a, int layer)
{
    int warp = (blockIdx.x * blockDim.x + threadIdx.x) >> 5;
    int lane = threadIdx.x & 31;
    if (warp >= N_NODES) return;

    const float4* xr = (const float4*)(x + (size_t)warp * EMB);
    float4 v = make_float4(0.f, 0.f, 0.f, 0.f);
    if (lane < EMB4) v = __ldg(xr + lane);

    float ss = v.x * v.x + v.y * v.y + v.z * v.z + v.w * v.w;
#pragma unroll
    for (int o = 16; o; o >>= 1) ss += __shfl_xor_sync(0xffffffffu, ss, o);

    float scale = __ldg(a + layer) / fmaxf(sqrtf(ss), EPSN);

    if (lane < EMB4) {
        float4* orow = (float4*)(out + (size_t)warp * EMB);
        float4 o;
        o.x = v.x * scale; o.y = v.y * scale; o.z = v.z * scale; o.w = v.w * scale;
        if (!FIRST) {
            float4 pv = orow[lane];
            o.x += pv.x; o.y += pv.y; o.z += pv.z; o.w += pv.w;
        }
        orow[lane] = o;
    }
}

// ---------------------------------------------------------------------------
// Launch: inputs are adj_row, adj_col, adj_val, embedding, a
// ---------------------------------------------------------------------------
extern "C" void kernel_launch(void* const* d_in, const int* in_sizes, int n_in,
                              void* d_out, int out_size)
{
    const int*   adj_row = (const int*)  d_in[0];
    const int*   adj_col = (const int*)  d_in[1];
    const float* adj_val = (const float*)d_in[2];
    const float* emb     = (const float*)d_in[3];
    const float* a       = (const float*)d_in[4];
    float*       out     = (float*)d_out;

    float* bufA;  cudaGetSymbolAddress((void**)&bufA,  g_bufA);
    float* bufB;  cudaGetSymbolAddress((void**)&bufB,  g_bufB);
    int*   deg;   cudaGetSymbolAddress((void**)&deg,   g_deg);
    int*   cur;   cudaGetSymbolAddress((void**)&cur,   g_cursor);
    int*   rp;    cudaGetSymbolAddress((void**)&rp,    g_rowptr);
    int*   bsum;  cudaGetSymbolAddress((void**)&bsum,  g_blocksum);
    int*   boff;  cudaGetSymbolAddress((void**)&boff,  g_blockoff);
    int2*  cells; cudaGetSymbolAddress((void**)&cells, g_cells);

    const int EB = (N_EDGES + 255) / 256;          // edge-parallel blocks
    const int ROWB = (N_NODES * 32 + 255) / 256;   // warp-per-row blocks

    // --- CSR build (amortized over 3 SpMM layers) ---
    zero_kernel<<<(N_NODES + 255) / 256, 256>>>(deg, cur);
    hist_kernel<<<EB, 256>>>(adj_row, deg);
    scan_k1<<<NB_SCAN, SCAN_B>>>(deg, bsum);
    scan_k2<<<1, SCAN_B>>>(bsum, boff);
    scan_k3<<<NB_SCAN, SCAN_B>>>(deg, boff, rp);
    scatter_kernel<<<EB, 256>>>(adj_row, adj_col, adj_val, rp, cur, cells);

    // --- 3 layers of SpMM + normalize-accumulate ---
    norm_add_kernel<true ><<<ROWB, 256>>>(emb,  out, a, 0);
    spmm_csr_kernel<<<ROWB, 256>>>(rp, cells, emb,  bufA);
    norm_add_kernel<false><<<ROWB, 256>>>(bufA, out, a, 1);
    spmm_csr_kernel<<<ROWB, 256>>>(rp, cells, bufA, bufB);
    norm_add_kernel<false><<<ROWB, 256>>>(bufB, out, a, 2);
    spmm_csr_kernel<<<ROWB, 256>>>(rp, cells, bufB, bufA);
    norm_add_kernel<false><<<ROWB, 256>>>(bufA, out, a, 3);
}

// round 3
// speedup vs baseline: 2.0940x; 1.7473x over previous
#include <cuda_runtime.h>
#include <cuda_fp16.h>

#define N_NODES 50000
#define N_EDGES 800000
#define EMB     100
#define EPSN    1e-12f
#define FULL    0xffffffffu

// Scratch (allocation-free rule: __device__ globals)
__device__ __half g_embH[N_NODES * EMB];
__device__ __half g_bufHA[N_NODES * EMB];
__device__ __half g_bufHB[N_NODES * EMB];
__device__ int    g_deg[N_NODES];
__device__ int    g_cursor[N_NODES];
__device__ int    g_rowptr[N_NODES];
__device__ int    g_counter;
__device__ int2   g_cells[N_EDGES];       // {col, val-as-int-bits}

// ---------------------------------------------------------------------------
// Layer 0: out = a0 * normalize(emb); embH = fp16(emb); zero deg/cursor/counter
// One warp per row (lanes 0..24 each own 4 dims).
// ---------------------------------------------------------------------------
__global__ void __launch_bounds__(256)
norm0_kernel(const float* __restrict__ emb, float* __restrict__ out,
             __half* __restrict__ embh, const float* __restrict__ a,
             int* __restrict__ deg, int* __restrict__ cur, int* __restrict__ counter)
{
    int t = blockIdx.x * blockDim.x + threadIdx.x;
    if (t < N_NODES) { deg[t] = 0; cur[t] = 0; }
    if (t == 0) *counter = 0;

    int warp = t >> 5;
    int lane = t & 31;
    if (warp >= N_NODES) return;

    float4 v = make_float4(0.f, 0.f, 0.f, 0.f);
    if (lane < 25) v = __ldg((const float4*)(emb + (size_t)warp * EMB) + lane);

    float ss = v.x * v.x + v.y * v.y + v.z * v.z + v.w * v.w;
#pragma unroll
    for (int o = 16; o; o >>= 1) ss += __shfl_xor_sync(FULL, ss, o);

    float scale = __ldg(a) / fmaxf(sqrtf(ss), EPSN);

    if (lane < 25) {
        float4 o;
        o.x = v.x * scale; o.y = v.y * scale; o.z = v.z * scale; o.w = v.w * scale;
        ((float4*)(out + (size_t)warp * EMB))[lane] = o;

        __half2 h0 = __floats2half2_rn(v.x, v.y);
        __half2 h1 = __floats2half2_rn(v.z, v.w);
        uint2 u;
        u.x = *(unsigned*)&h0; u.y = *(unsigned*)&h1;
        ((uint2*)(embh + (size_t)warp * EMB))[lane] = u;
    }
}

// ---------------------------------------------------------------------------
// CSR build: histogram -> warp-aggregated atomic offsets -> scatter
// ---------------------------------------------------------------------------
__global__ void hist_kernel(const int* __restrict__ rows, int* __restrict__ deg)
{
    int e = blockIdx.x * blockDim.x + threadIdx.x;
    if (e < N_EDGES) atomicAdd(&deg[rows[e]], 1);
}

__global__ void offsets_kernel(const int* __restrict__ deg, int* __restrict__ rowptr,
                               int* __restrict__ counter)
{
    int i = blockIdx.x * blockDim.x + threadIdx.x;
    int lane = threadIdx.x & 31;
    int d = (i < N_NODES) ? deg[i] : 0;

    int s = d;                                   // warp inclusive scan
#pragma unroll
    for (int o = 1; o < 32; o <<= 1) {
        int t = __shfl_up_sync(FULL, s, o);
        if (lane >= o) s += t;
    }
    int total = __shfl_sync(FULL, s, 31);
    int base = 0;
    if (lane == 31) base = atomicAdd(counter, total);
    base = __shfl_sync(FULL, base, 31);
    if (i < N_NODES) rowptr[i] = base + s - d;   // exclusive within warp
}

__global__ void scatter_kernel(const int* __restrict__ rows,
                               const int* __restrict__ cols,
                               const float* __restrict__ vals,
                               const int* __restrict__ rowptr,
                               int* __restrict__ cur, int2* __restrict__ cells)
{
    int e = blockIdx.x * blockDim.x + threadIdx.x;
    if (e >= N_EDGES) return;
    int r = rows[e];
    int pos = rowptr[r] + atomicAdd(&cur[r], 1);
    cells[pos] = make_int2(cols[e], __float_as_int(vals[e]));
}

// ---------------------------------------------------------------------------
// Fused SpMM + normalize + accumulate. Warp per row.
// Gathers fp16 rows, accumulates fp32, then in-register: out += a*acc/||acc||.
// WRITE_NEXT: also emit fp16(acc) for the next layer's gather.
// ---------------------------------------------------------------------------
template<bool WRITE_NEXT>
__global__ void __launch_bounds__(256)
spmm_fused_kernel(const int* __restrict__ rowptr, const int* __restrict__ deg,
                  const int2* __restrict__ cells, const __half* __restrict__ xh,
                  __half* __restrict__ yh, float* __restrict__ out,
                  const float* __restrict__ a, int layer)
{
    int warp = (blockIdx.x * blockDim.x + threadIdx.x) >> 5;
    int lane = threadIdx.x & 31;
    if (warp >= N_NODES) return;

    int p   = __ldg(rowptr + warp);
    int end = p + __ldg(deg + warp);

    float4 acc = make_float4(0.f, 0.f, 0.f, 0.f);
    bool act = lane < 25;

    for (; p + 1 < end; p += 2) {
        int2 cv0 = __ldg(cells + p);
        int2 cv1 = __ldg(cells + p + 1);
        if (act) {
            uint2 u0 = __ldg((const uint2*)(xh + (size_t)cv0.x * EMB) + lane);
            uint2 u1 = __ldg((const uint2*)(xh + (size_t)cv1.x * EMB) + lane);
            float w0 = __int_as_float(cv0.y);
            float w1 = __int_as_float(cv1.y);
            float2 p0 = __half22float2(*(__half2*)&u0.x);
            float2 q0 = __half22float2(*(__half2*)&u0.y);
            float2 p1 = __half22float2(*(__half2*)&u1.x);
            float2 q1 = __half22float2(*(__half2*)&u1.y);
            acc.x += w0 * p0.x; acc.y += w0 * p0.y;
            acc.z += w0 * q0.x; acc.w += w0 * q0.y;
            acc.x += w1 * p1.x; acc.y += w1 * p1.y;
            acc.z += w1 * q1.x; acc.w += w1 * q1.y;
        }
    }
    if (p < end) {
        int2 cv = __ldg(cells + p);
        if (act) {
            uint2 u = __ldg((const uint2*)(xh + (size_t)cv.x * EMB) + lane);
            float w = __int_as_float(cv.y);
            float2 pp = __half22float2(*(__half2*)&u.x);
            float2 qq = __half22float2(*(__half2*)&u.y);
            acc.x += w * pp.x; acc.y += w * pp.y;
            acc.z += w * qq.x; acc.w += w * qq.y;
        }
    }

    // normalize + accumulate (full row lives in the warp's registers)
    float ss = acc.x * acc.x + acc.y * acc.y + acc.z * acc.z + acc.w * acc.w;
#pragma unroll
    for (int o = 16; o; o >>= 1) ss += __shfl_xor_sync(FULL, ss, o);

    float scale = __ldg(a + layer) / fmaxf(sqrtf(ss), EPSN);

    if (act) {
        if (WRITE_NEXT) {
            __half2 h0 = __floats2half2_rn(acc.x, acc.y);
            __half2 h1 = __floats2half2_rn(acc.z, acc.w);
            uint2 u;
            u.x = *(unsigned*)&h0; u.y = *(unsigned*)&h1;
            ((uint2*)(yh + (size_t)warp * EMB))[lane] = u;
        }
        float4* orow = (float4*)(out + (size_t)warp * EMB);
        float4 pv = orow[lane];
        pv.x += scale * acc.x; pv.y += scale * acc.y;
        pv.z += scale * acc.z; pv.w += scale * acc.w;
        orow[lane] = pv;
    }
}

// ---------------------------------------------------------------------------
// Launch: inputs are adj_row, adj_col, adj_val, embedding, a
// ---------------------------------------------------------------------------
extern "C" void kernel_launch(void* const* d_in, const int* in_sizes, int n_in,
                              void* d_out, int out_size)
{
    const int*   adj_row = (const int*)  d_in[0];
    const int*   adj_col = (const int*)  d_in[1];
    const float* adj_val = (const float*)d_in[2];
    const float* emb     = (const float*)d_in[3];
    const float* a       = (const float*)d_in[4];
    float*       out     = (float*)d_out;

    __half* embh; cudaGetSymbolAddress((void**)&embh, g_embH);
    __half* bufA; cudaGetSymbolAddress((void**)&bufA, g_bufHA);
    __half* bufB; cudaGetSymbolAddress((void**)&bufB, g_bufHB);
    int*   deg;   cudaGetSymbolAddress((void**)&deg,   g_deg);
    int*   cur;   cudaGetSymbolAddress((void**)&cur,   g_cursor);
    int*   rp;    cudaGetSymbolAddress((void**)&rp,    g_rowptr);
    int*   cnt;   cudaGetSymbolAddress((void**)&cnt,   g_counter);
    int2*  cells; cudaGetSymbolAddress((void**)&cells, g_cells);

    const int EB   = (N_EDGES + 255) / 256;
    const int ROWB = (N_NODES * 32 + 255) / 256;
    const int NODB = (N_NODES + 255) / 256;

    // layer 0 + init
    norm0_kernel<<<ROWB, 256>>>(emb, out, embh, a, deg, cur, cnt);
    // CSR build
    hist_kernel<<<EB, 256>>>(adj_row, deg);
    offsets_kernel<<<NODB, 256>>>(deg, rp, cnt);
    scatter_kernel<<<EB, 256>>>(adj_row, adj_col, adj_val, rp, cur, cells);
    // 3 fused SpMM + normalize + accumulate layers
    spmm_fused_kernel<true ><<<ROWB, 256>>>(rp, deg, cells, embh, bufA, out, a, 1);
    spmm_fused_kernel<true ><<<ROWB, 256>>>(rp, deg, cells, bufA, bufB, out, a, 2);
    spmm_fused_kernel<false><<<ROWB, 256>>>(rp, deg, cells, bufB, nullptr, out, a, 3);
}